// round 4
// baseline (speedup 1.0000x reference)
#include <cuda_runtime.h>
#include <math.h>
#include <stdint.h>

// ---------------- constants ----------------
#define NCHUNK 32
#define EVCAP  204800

// ---------------- device scratch (single symbol, offsets) ----------------
static constexpr size_t O_KV = 0;                                   // (EVCAP,512) k|v
static constexpr size_t O_NW = O_KV + (size_t)EVCAP * 512;          // 4096x512
static constexpr size_t O_TW = O_NW + (size_t)4096 * 512;           // 1024x512
static constexpr size_t O_VW = O_TW + (size_t)1024 * 512;           // 256x512
static constexpr size_t O_CS = O_VW + (size_t)256 * 512;            // 512 colsum
static constexpr size_t O_Q  = O_CS + 512;                          // (H,64,32)
static constexpr size_t O_PO = O_Q + 8 * 64 * 32;                   // (B,H,NCHUNK,64,32)
static constexpr size_t O_PZ = O_PO + (size_t)16 * 8 * NCHUNK * 64 * 32; // (B,H,NCHUNK,64)
static constexpr size_t O_LAT = O_PZ + (size_t)16 * 8 * NCHUNK * 64;
static constexpr size_t O_LN  = O_LAT + 1024 * 256;
static constexpr size_t O_T1  = O_LN + 1024 * 256;                  // 1024x1024
static constexpr size_t O_T2  = O_T1 + 1024 * 1024;                 // 1024x768
static constexpr size_t O_AT  = O_T2 + 1024 * 768;
static constexpr size_t O_XB  = O_AT + 1024 * 256;
static constexpr size_t O_KB  = O_XB + 1024 * 256;                  // 1024x512
static constexpr size_t O_QB  = O_KB + 1024 * 512;                  // (H,2,32)
static constexpr size_t O_BO  = O_QB + 512;                         // (B,2,256)
static constexpr size_t O_MEAN = O_BO + 16 * 2 * 256;               // (B,256)
static constexpr size_t SCRATCH_TOTAL = O_MEAN + 16 * 256;

__device__ float g_buf[SCRATCH_TOTAL];

__device__ __forceinline__ float gelu_f(float x) {
    float x3 = x * x * x;
    return 0.5f * x * (1.0f + tanhf(0.7978845608028654f * (x + 0.044715f * x3)));
}

// ---------------- generic tiled GEMM + epilogue ----------------
// C(MxN) = A(MxK) @ W(KxN); optional bias[c], gelu, residual res[(r%resMod)*N + c]
// Requires M%64==0, N%64==0, K%16==0.
__global__ __launch_bounds__(256) void gemm_epi(
    const float* __restrict__ A, const float* __restrict__ W, float* __restrict__ C,
    int M, int K, int N, const float* __restrict__ res, int resMod,
    const float* __restrict__ bias, int doGelu)
{
    __shared__ float As[16][68];
    __shared__ float Bs[16][64];
    int t = threadIdx.x;
    int tx = t & 15, ty = t >> 4;
    int row0 = blockIdx.y * 64, col0 = blockIdx.x * 64;
    float acc[4][4] = {};
    int ar = t >> 2, ac = (t & 3) * 4;
    int br = t >> 4, bc = (t & 15) * 4;
    for (int k0 = 0; k0 < K; k0 += 16) {
        float4 a4 = *(const float4*)(A + (size_t)(row0 + ar) * K + k0 + ac);
        As[ac + 0][ar] = a4.x; As[ac + 1][ar] = a4.y;
        As[ac + 2][ar] = a4.z; As[ac + 3][ar] = a4.w;
        *(float4*)&Bs[br][bc] = *(const float4*)(W + (size_t)(k0 + br) * N + col0 + bc);
        __syncthreads();
#pragma unroll
        for (int kk = 0; kk < 16; kk++) {
            float4 av = *(const float4*)&As[kk][ty * 4];
            float4 bv = *(const float4*)&Bs[kk][tx * 4];
            acc[0][0] += av.x * bv.x; acc[0][1] += av.x * bv.y; acc[0][2] += av.x * bv.z; acc[0][3] += av.x * bv.w;
            acc[1][0] += av.y * bv.x; acc[1][1] += av.y * bv.y; acc[1][2] += av.y * bv.z; acc[1][3] += av.y * bv.w;
            acc[2][0] += av.z * bv.x; acc[2][1] += av.z * bv.y; acc[2][2] += av.z * bv.z; acc[2][3] += av.z * bv.w;
            acc[3][0] += av.w * bv.x; acc[3][1] += av.w * bv.y; acc[3][2] += av.w * bv.z; acc[3][3] += av.w * bv.w;
        }
        __syncthreads();
    }
#pragma unroll
    for (int i = 0; i < 4; i++) {
        int r = row0 + ty * 4 + i;
#pragma unroll
        for (int j = 0; j < 4; j++) {
            int c = col0 + tx * 4 + j;
            float v = acc[i][j];
            if (bias) v += bias[c];
            if (doGelu) v = gelu_f(v);
            if (res) v += res[(size_t)(r % resMod) * N + c];
            C[(size_t)r * N + c] = v;
        }
    }
}

// ---------------- colsum of Wkv (512) ----------------
__global__ void colsum_kernel(const float* __restrict__ Wkv, float* __restrict__ cs) {
    int c = threadIdx.x;  // 512 threads
    float s = 0.f;
    for (int k = 0; k < 256; k++) s += Wkv[k * 512 + c];
    cs[c] = s;
}

// ---------------- per-event KV: LN stats from raw rows, combine projected rows ----------------
__global__ __launch_bounds__(256) void event_kv_kernel(
    const int* __restrict__ nid, const int* __restrict__ tbi, const int* __restrict__ vli,
    const float* __restrict__ nemb, const float* __restrict__ temb, const float* __restrict__ vemb,
    const float* __restrict__ nW, const float* __restrict__ tW, const float* __restrict__ vW,
    const float* __restrict__ colsum, float* __restrict__ KV, int E)
{
    __shared__ float sMean[32], sInv[32];
    __shared__ int sNi[32], sTi[32], sVi[32];
    int t = threadIdx.x;
    int le = t >> 3, g8 = t & 7;
    int base = blockIdx.x * 32;
    int e = base + le;
    float s = 0.f, sq = 0.f;
    if (e < E) {
        int ni = nid[e], ti = tbi[e], vi = vli[e];
        if (g8 == 0) { sNi[le] = ni; sTi[le] = ti; sVi[le] = vi; }
        const float* np = nemb + (size_t)ni * 256;
        const float* tp = temb + (size_t)ti * 256;
        const float* vp = vemb + (size_t)vi * 256;
#pragma unroll
        for (int i = 0; i < 8; i++) {
            int d = g8 * 32 + i * 4;
            float4 a = *(const float4*)(np + d);
            float4 b = *(const float4*)(tp + d);
            float4 c = *(const float4*)(vp + d);
            float x0 = a.x + b.x + c.x, x1 = a.y + b.y + c.y;
            float x2 = a.z + b.z + c.z, x3 = a.w + b.w + c.w;
            s += x0 + x1 + x2 + x3;
            sq += x0 * x0 + x1 * x1 + x2 * x2 + x3 * x3;
        }
    }
    s += __shfl_xor_sync(0xffffffffu, s, 1);
    s += __shfl_xor_sync(0xffffffffu, s, 2);
    s += __shfl_xor_sync(0xffffffffu, s, 4);
    sq += __shfl_xor_sync(0xffffffffu, sq, 1);
    sq += __shfl_xor_sync(0xffffffffu, sq, 2);
    sq += __shfl_xor_sync(0xffffffffu, sq, 4);
    if (g8 == 0 && e < E) {
        float mean = s * (1.0f / 256.0f);
        float var = sq * (1.0f / 256.0f) - mean * mean;
        sMean[le] = mean;
        sInv[le] = rsqrtf(var + 1e-5f);
    }
    __syncthreads();
    int nE = E - base; if (nE > 32) nE = 32;
    float cs0 = colsum[t], cs1 = colsum[t + 256];
#pragma unroll 4
    for (int ee = 0; ee < nE; ee++) {
        int ni = sNi[ee], ti = sTi[ee], vi = sVi[ee];
        float inv = sInv[ee];
        float mi = sMean[ee] * inv;
        float p0 = nW[(size_t)ni * 512 + t] + tW[(size_t)ti * 512 + t] + vW[(size_t)vi * 512 + t];
        float p1 = nW[(size_t)ni * 512 + 256 + t] + tW[(size_t)ti * 512 + 256 + t] + vW[(size_t)vi * 512 + 256 + t];
        KV[(size_t)(base + ee) * 512 + t] = inv * p0 - mi * cs0;
        KV[(size_t)(base + ee) * 512 + 256 + t] = inv * p1 - mi * cs1;
    }
}

// ---------------- generic LayerNorm: one warp per row, 256-dim ----------------
__global__ void ln_kernel(const float* __restrict__ X, float* __restrict__ Y,
                          const float* __restrict__ w, const float* __restrict__ b, int rows)
{
    int row = blockIdx.x * 8 + (threadIdx.x >> 5);
    int lane = threadIdx.x & 31;
    if (row >= rows) return;
    const float* x = X + (size_t)row * 256;
    float v[8]; float s = 0.f, sq = 0.f;
#pragma unroll
    for (int i = 0; i < 8; i++) { v[i] = x[lane + 32 * i]; s += v[i]; sq += v[i] * v[i]; }
#pragma unroll
    for (int o = 16; o > 0; o >>= 1) {
        s += __shfl_xor_sync(0xffffffffu, s, o);
        sq += __shfl_xor_sync(0xffffffffu, sq, o);
    }
    float mean = s * (1.0f / 256.0f);
    float var = sq * (1.0f / 256.0f) - mean * mean;
    float inv = rsqrtf(var + 1e-5f);
    float* y = Y + (size_t)row * 256;
#pragma unroll
    for (int i = 0; i < 8; i++) {
        int d = lane + 32 * i;
        float o = (v[i] - mean) * inv;
        if (w) o = o * w[d] + b[d];
        y[d] = o;
    }
}

// ---------------- cross-attn Q: ln(lat_init) @ Wq -> heads, pre-scaled ----------------
__global__ void qc_kernel(const float* __restrict__ lnlat, const float* __restrict__ Wq,
                          float* __restrict__ qout)
{
    int l = blockIdx.x;        // 64
    int c = threadIdx.x;       // 256
    float s = 0.f;
    for (int k = 0; k < 256; k++) s += lnlat[l * 256 + k] * Wq[k * 256 + c];
    int h = c >> 5, dh = c & 31;
    qout[(h * 64 + l) * 32 + dh] = s * 0.17677669529663689f;  // 1/sqrt(32)
}

// ---------------- cross-attn scan over ragged events (deterministic) ----------------
__global__ __launch_bounds__(256) void attn_scan_kernel(
    const int* __restrict__ bidx, const float* __restrict__ KV, const float* __restrict__ qg,
    float* __restrict__ pO, float* __restrict__ pZ, int E)
{
    int chunk = blockIdx.x, b = blockIdx.y, h = blockIdx.z;
    int per = (E + NCHUNK - 1) / NCHUNK;
    int s0 = chunk * per;
    int s1 = s0 + per; if (s1 > E) s1 = E;
    __shared__ float sq[2048];
    __shared__ int list[256];
    __shared__ int wcnt[8];
    int t = threadIdx.x;
    for (int i = t; i < 2048; i += 256) sq[i] = qg[h * 2048 + i];
    __syncthreads();
    int l = t >> 2, r = t & 3;
    float qv[8];
#pragma unroll
    for (int j = 0; j < 8; j++) qv[j] = sq[l * 32 + r * 8 + j];
    float accO[8] = {0.f, 0.f, 0.f, 0.f, 0.f, 0.f, 0.f, 0.f};
    float accZ = 0.f;
    int w = t >> 5, lane = t & 31;
    for (int base = s0; base < s1; base += 256) {
        int e = base + t;
        bool m = (e < s1) && (bidx[e] == b);
        unsigned bm = __ballot_sync(0xffffffffu, m);
        if (lane == 0) wcnt[w] = __popc(bm);
        __syncthreads();
        int ofs = 0, total = 0;
#pragma unroll
        for (int ww = 0; ww < 8; ww++) { int c = wcnt[ww]; if (ww < w) ofs += c; total += c; }
        if (m) list[ofs + __popc(bm & ((1u << lane) - 1u))] = e;
        __syncthreads();
        for (int i = 0; i < total; i++) {
            int ev = list[i];
            const float* kp = KV + (size_t)ev * 512 + h * 32 + r * 8;
            float4 k0 = *(const float4*)kp;
            float4 k1 = *(const float4*)(kp + 4);
            float part = qv[0] * k0.x + qv[1] * k0.y + qv[2] * k0.z + qv[3] * k0.w
                       + qv[4] * k1.x + qv[5] * k1.y + qv[6] * k1.z + qv[7] * k1.w;
            part += __shfl_xor_sync(0xffffffffu, part, 1);
            part += __shfl_xor_sync(0xffffffffu, part, 2);
            float p = __expf(part);
            if (r == 0) accZ += p;
            float4 v0 = *(const float4*)(kp + 256);
            float4 v1 = *(const float4*)(kp + 260);
            accO[0] += p * v0.x; accO[1] += p * v0.y; accO[2] += p * v0.z; accO[3] += p * v0.w;
            accO[4] += p * v1.x; accO[5] += p * v1.y; accO[6] += p * v1.z; accO[7] += p * v1.w;
        }
        __syncthreads();
    }
    size_t pb = (size_t)((b * 8 + h) * NCHUNK + chunk);
#pragma unroll
    for (int j = 0; j < 8; j++) pO[pb * 2048 + l * 32 + r * 8 + j] = accO[j];
    if (r == 0) pZ[pb * 64 + l] = accZ;
}

// ---------------- combine chunk partials -> attn output (B*L, 256) ----------------
__global__ void attn_combine_kernel(const float* __restrict__ pO, const float* __restrict__ pZ,
                                    float* __restrict__ attn)
{
    int bh = blockIdx.x;        // 0..127
    int b = bh >> 3, h = bh & 7;
    int t = threadIdx.x;
    __shared__ float sz[64];
    if (t < 64) {
        float z = 0.f;
        for (int c = 0; c < NCHUNK; c++) z += pZ[((size_t)bh * NCHUNK + c) * 64 + t];
        sz[t] = 1.0f / z;
    }
    __syncthreads();
    for (int i = t; i < 2048; i += 256) {
        int l = i >> 5, d = i & 31;
        float s = 0.f;
        for (int c = 0; c < NCHUNK; c++) s += pO[((size_t)bh * NCHUNK + c) * 2048 + i];
        attn[(size_t)(b * 64 + l) * 256 + h * 32 + d] = s * sz[l];
    }
}

// ---------------- small self-attention over latents, per (b,h) ----------------
__global__ __launch_bounds__(256) void self_attn_kernel(const float* __restrict__ qkv,
                                                        float* __restrict__ out)
{
    int b = blockIdx.x, h = blockIdx.y;
    __shared__ float sk[2048], sv[2048];
    int t = threadIdx.x;
    for (int i = t; i < 2048; i += 256) {
        int key = i >> 5, d = i & 31;
        size_t rowb = (size_t)(b * 64 + key) * 768;
        sk[i] = qkv[rowb + 256 + h * 32 + d];
        sv[i] = qkv[rowb + 512 + h * 32 + d];
    }
    __syncthreads();
    int ql = t >> 2, r = t & 3;
    const float* qp = qkv + (size_t)(b * 64 + ql) * 768 + h * 32 + r * 8;
    float qv[8];
#pragma unroll
    for (int j = 0; j < 8; j++) qv[j] = qp[j] * 0.17677669529663689f;
    float z = 0.f;
    for (int key = 0; key < 64; key++) {
        float part = 0.f;
#pragma unroll
        for (int j = 0; j < 8; j++) part += qv[j] * sk[key * 32 + r * 8 + j];
        part += __shfl_xor_sync(0xffffffffu, part, 1);
        part += __shfl_xor_sync(0xffffffffu, part, 2);
        z += __expf(part);
    }
    float o[8] = {0.f, 0.f, 0.f, 0.f, 0.f, 0.f, 0.f, 0.f};
    for (int key = 0; key < 64; key++) {
        float part = 0.f;
#pragma unroll
        for (int j = 0; j < 8; j++) part += qv[j] * sk[key * 32 + r * 8 + j];
        part += __shfl_xor_sync(0xffffffffu, part, 1);
        part += __shfl_xor_sync(0xffffffffu, part, 2);
        float p = __expf(part);
#pragma unroll
        for (int j = 0; j < 8; j++) o[j] += p * sv[key * 32 + r * 8 + j];
    }
    float invz = 1.0f / z;
#pragma unroll
    for (int j = 0; j < 8; j++)
        out[(size_t)(b * 64 + ql) * 256 + h * 32 + r * 8 + j] = o[j] * invz;
}

// ---------------- behavior query: (bh_query @ bh_wq) -> heads, pre-scaled ----------------
__global__ void qb_kernel(const float* __restrict__ bhq, const float* __restrict__ wq,
                          float* __restrict__ qb)
{
    int t = threadIdx.x;  // 512
    int be = t >> 8, c = t & 255;
    float s = 0.f;
    for (int k = 0; k < 256; k++) s += bhq[be * 256 + k] * wq[k * 256 + c];
    int h = c >> 5, dh = c & 31;
    qb[(h * 2 + be) * 32 + dh] = s * 0.17677669529663689f;
}

// ---------------- behavior attention per (b,h): 2 queries x 64 keys ----------------
__global__ void bh_attn_kernel(const float* __restrict__ kvb, const float* __restrict__ qb,
                               float* __restrict__ bo)
{
    int b = blockIdx.x, h = blockIdx.y;
    __shared__ float sk[2048], sv[2048];
    int t = threadIdx.x;  // 64
    for (int i = t; i < 2048; i += 64) {
        int key = i >> 5, d = i & 31;
        size_t rowb = (size_t)(b * 64 + key) * 512;
        sk[i] = kvb[rowb + h * 32 + d];
        sv[i] = kvb[rowb + 256 + h * 32 + d];
    }
    __syncthreads();
    int be = t >> 5, d = t & 31;
    float q[32];
#pragma unroll
    for (int j = 0; j < 32; j++) q[j] = qb[(h * 2 + be) * 32 + j];
    float z = 0.f, o = 0.f;
    for (int key = 0; key < 64; key++) {
        float s = 0.f;
#pragma unroll
        for (int j = 0; j < 32; j++) s += q[j] * sk[key * 32 + j];
        float p = __expf(s);
        z += p;
        o += p * sv[key * 32 + d];
    }
    bo[(size_t)(b * 2 + be) * 256 + h * 32 + d] = o / z;
}

// ---------------- behavior output: bo(32x256) @ wo(256) -> d_out[0..32) ----------------
__global__ void bh_out_kernel(const float* __restrict__ bo, const float* __restrict__ wo,
                              float* __restrict__ outBeh)
{
    int t = threadIdx.x;  // 1024
    int row = t >> 5, lane = t & 31;
    float s = 0.f;
#pragma unroll
    for (int i = 0; i < 8; i++) s += bo[row * 256 + lane + 32 * i] * wo[lane + 32 * i];
#pragma unroll
    for (int o = 16; o > 0; o >>= 1) s += __shfl_xor_sync(0xffffffffu, s, o);
    if (lane == 0) outBeh[row] = s;
}

// ---------------- mean over latents ----------------
__global__ void mean_kernel(const float* __restrict__ lat, float* __restrict__ mn)
{
    int b = blockIdx.x, d = threadIdx.x;  // 256
    float s = 0.f;
    for (int l = 0; l < 64; l++) s += lat[(size_t)(b * 64 + l) * 256 + d];
    mn[b * 256 + d] = s * (1.0f / 64.0f);
}

// ---------------- logits: mean(16x256) @ sp_w(256x64) + sp_b ----------------
__global__ void logits_kernel(const float* __restrict__ mn, const float* __restrict__ spw,
                              const float* __restrict__ spb, float* __restrict__ out)
{
    int t = threadIdx.x;  // 1024
    int b = t >> 6, s = t & 63;
    float acc = spb[s];
    for (int k = 0; k < 256; k++) acc += mn[b * 256 + k] * spw[k * 64 + s];
    out[b * 64 + s] = acc;
}

// ---------------- host launcher ----------------
extern "C" void kernel_launch(void* const* d_in, const int* in_sizes, int n_in,
                              void* d_out, int out_size)
{
    // Resolve input ordering: if first four sizes are equal, index arrays come first
    // (setup_inputs dict order); otherwise weights first (reference signature order).
    int ib, wb;
    if (in_sizes[0] == in_sizes[1] && in_sizes[1] == in_sizes[2] && in_sizes[2] == in_sizes[3]) {
        ib = 0; wb = n_in - 21;
    } else {
        wb = 0; ib = 21;
    }
    const int* nid  = (const int*)d_in[ib + 0];
    const int* tbi  = (const int*)d_in[ib + 1];
    const int* vli  = (const int*)d_in[ib + 2];
    const int* bidx = (const int*)d_in[ib + 3];
    int E = in_sizes[ib];
    if (E > EVCAP) E = EVCAP;

    const float* nemb    = (const float*)d_in[wb + 0];
    const float* temb    = (const float*)d_in[wb + 1];
    const float* vemb    = (const float*)d_in[wb + 2];
    const float* lat0    = (const float*)d_in[wb + 3];
    const float* Wq_c    = (const float*)d_in[wb + 4];
    const float* Wkv_c   = (const float*)d_in[wb + 5];
    const float* Wo_c    = (const float*)d_in[wb + 6];
    const float* W1_c    = (const float*)d_in[wb + 7];
    const float* W2_c    = (const float*)d_in[wb + 8];
    const float* Wqkv_s  = (const float*)d_in[wb + 9];
    const float* Wo_s    = (const float*)d_in[wb + 10];
    const float* W1_s    = (const float*)d_in[wb + 11];
    const float* W2_s    = (const float*)d_in[wb + 12];
    const float* bh_query = (const float*)d_in[wb + 13];
    const float* bh_wq   = (const float*)d_in[wb + 14];
    const float* bh_wkv  = (const float*)d_in[wb + 15];
    const float* bh_wo   = (const float*)d_in[wb + 16];
    const float* bh_ln_w = (const float*)d_in[wb + 17];
    const float* bh_ln_b = (const float*)d_in[wb + 18];
    const float* sp_w    = (const float*)d_in[wb + 19];
    const float* sp_b    = (const float*)d_in[wb + 20];

    float* buf = nullptr;
    cudaGetSymbolAddress((void**)&buf, g_buf);
    float* KV   = buf + O_KV;
    float* nW   = buf + O_NW;
    float* tW   = buf + O_TW;
    float* vW   = buf + O_VW;
    float* CS   = buf + O_CS;
    float* Qg   = buf + O_Q;
    float* PO   = buf + O_PO;
    float* PZ   = buf + O_PZ;
    float* LAT  = buf + O_LAT;
    float* LNB  = buf + O_LN;
    float* T1   = buf + O_T1;
    float* T2   = buf + O_T2;
    float* AT   = buf + O_AT;
    float* XB   = buf + O_XB;
    float* KB   = buf + O_KB;
    float* QB   = buf + O_QB;
    float* BO   = buf + O_BO;
    float* MN   = buf + O_MEAN;
    float* out = (float*)d_out;

    // --- Phase A: KV projection via precomputed embedding projections ---
    gemm_epi<<<dim3(8, 64), 256>>>(nemb, Wkv_c, nW, 4096, 256, 512, nullptr, 1, nullptr, 0);
    gemm_epi<<<dim3(8, 16), 256>>>(temb, Wkv_c, tW, 1024, 256, 512, nullptr, 1, nullptr, 0);
    gemm_epi<<<dim3(8, 4), 256>>>(vemb, Wkv_c, vW, 256, 256, 512, nullptr, 1, nullptr, 0);
    colsum_kernel<<<1, 512>>>(Wkv_c, CS);
    int EB = (E + 31) / 32;
    event_kv_kernel<<<EB, 256>>>(nid, tbi, vli, nemb, temb, vemb, nW, tW, vW, CS, KV, E);

    // --- Cross-attention ---
    ln_kernel<<<8, 256>>>(lat0, LNB, nullptr, nullptr, 64);
    qc_kernel<<<64, 256>>>(LNB, Wq_c, Qg);
    attn_scan_kernel<<<dim3(NCHUNK, 16, 8), 256>>>(bidx, KV, Qg, PO, PZ, E);
    attn_combine_kernel<<<128, 256>>>(PO, PZ, AT);

    // lat = lat_init + attn @ Wo_c
    gemm_epi<<<dim3(4, 16), 256>>>(AT, Wo_c, LAT, 1024, 256, 256, lat0, 64, nullptr, 0);
    // lat += gelu(ln(lat) @ W1_c) @ W2_c
    ln_kernel<<<128, 256>>>(LAT, LNB, nullptr, nullptr, 1024);
    gemm_epi<<<dim3(16, 16), 256>>>(LNB, W1_c, T1, 1024, 256, 1024, nullptr, 1, nullptr, 1);
    gemm_epi<<<dim3(4, 16), 256>>>(T1, W2_c, LAT, 1024, 1024, 256, LAT, 1024, nullptr, 0);

    // --- Self-attention layers ---
    for (int i = 0; i < 2; i++) {
        ln_kernel<<<128, 256>>>(LAT, LNB, nullptr, nullptr, 1024);
        gemm_epi<<<dim3(12, 16), 256>>>(LNB, Wqkv_s + (size_t)i * 256 * 768, T2, 1024, 256, 768,
                                        nullptr, 1, nullptr, 0);
        self_attn_kernel<<<dim3(16, 8), 256>>>(T2, AT);
        gemm_epi<<<dim3(4, 16), 256>>>(AT, Wo_s + (size_t)i * 256 * 256, LAT, 1024, 256, 256,
                                       LAT, 1024, nullptr, 0);
        ln_kernel<<<128, 256>>>(LAT, LNB, nullptr, nullptr, 1024);
        gemm_epi<<<dim3(16, 16), 256>>>(LNB, W1_s + (size_t)i * 256 * 1024, T1, 1024, 256, 1024,
                                        nullptr, 1, nullptr, 1);
        gemm_epi<<<dim3(4, 16), 256>>>(T1, W2_s + (size_t)i * 1024 * 256, LAT, 1024, 1024, 256,
                                       LAT, 1024, nullptr, 0);
    }

    // --- Behavior decoder ---
    ln_kernel<<<128, 256>>>(LAT, XB, bh_ln_w, bh_ln_b, 1024);
    qb_kernel<<<1, 512>>>(bh_query, bh_wq, QB);
    gemm_epi<<<dim3(8, 16), 256>>>(XB, bh_wkv, KB, 1024, 256, 512, nullptr, 1, nullptr, 0);
    bh_attn_kernel<<<dim3(16, 8), 64>>>(KB, QB, BO);
    bh_out_kernel<<<1, 1024>>>(BO, bh_wo, out);

    // --- Spike head ---
    mean_kernel<<<16, 256>>>(LAT, MN);
    logits_kernel<<<1, 1024>>>(MN, sp_w, sp_b, out + 32);
}